// round 4
// baseline (speedup 1.0000x reference)
#include <cuda_runtime.h>
#include <cuda_fp16.h>
#include <cstdint>

#define NTHREADS 256
#define NBLOCKS  148

// ---------------- PTX helpers ----------------
__device__ __forceinline__ uint32_t smem_u32(const void* p) {
    uint32_t a;
    asm("{ .reg .u64 t; cvta.to.shared.u64 t, %1; cvt.u32.u64 %0, t; }" : "=r"(a) : "l"(p));
    return a;
}
__device__ __forceinline__ void ldmx2(uint32_t& r0, uint32_t& r1, uint32_t addr) {
    asm volatile("ldmatrix.sync.aligned.m8n8.x2.shared.b16 {%0,%1}, [%2];"
                 : "=r"(r0), "=r"(r1) : "r"(addr));
}
__device__ __forceinline__ void ldmx4(uint32_t& r0, uint32_t& r1, uint32_t& r2, uint32_t& r3,
                                      uint32_t addr) {
    asm volatile("ldmatrix.sync.aligned.m8n8.x4.shared.b16 {%0,%1,%2,%3}, [%4];"
                 : "=r"(r0), "=r"(r1), "=r"(r2), "=r"(r3) : "r"(addr));
}
__device__ __forceinline__ void mma_k8(float* d, uint32_t a0, uint32_t a1, uint32_t b0) {
    asm volatile("mma.sync.aligned.m16n8k8.row.col.f32.f16.f16.f32 "
                 "{%0,%1,%2,%3}, {%4,%5}, {%6}, {%0,%1,%2,%3};"
                 : "+f"(d[0]), "+f"(d[1]), "+f"(d[2]), "+f"(d[3])
                 : "r"(a0), "r"(a1), "r"(b0));
}
__device__ __forceinline__ void mma_k16(float* d, uint32_t a0, uint32_t a1, uint32_t a2,
                                        uint32_t a3, uint32_t b0, uint32_t b1) {
    asm volatile("mma.sync.aligned.m16n8k16.row.col.f32.f16.f16.f32 "
                 "{%0,%1,%2,%3}, {%4,%5,%6,%7}, {%8,%9}, {%0,%1,%2,%3};"
                 : "+f"(d[0]), "+f"(d[1]), "+f"(d[2]), "+f"(d[3])
                 : "r"(a0), "r"(a1), "r"(a2), "r"(a3), "r"(b0), "r"(b1));
}
__device__ __forceinline__ uint32_t pack_h2(float x, float y) {
    __half2 h = __floats2half2_rn(x, y);          // low half = x
    return *reinterpret_cast<uint32_t*>(&h);
}

// ---------------- shared memory ----------------
struct SmemT {
    __align__(16) uint8_t w2t[128 * 256];   // W2^T [n][k] half, swizzled 256B rows (32 KB)
    __align__(16) __half  w1t[128 * 8];     // W1^T [n][k0..6], k7 = b1[n]          (2 KB)
    __align__(16) __half  inv[128 * 8];     // per-row invariants (k7 = 1.0)        (2 KB)
    __align__(16) float   scal[128 * 8];    // per-row {a,b,c,d,r00,r01,-,-}        (4 KB)
    __align__(16) float   w3[128 * 4];      // W3 rows as float4                    (2 KB)
    __align__(16) float   part[2 * 128 * 4];// layer-3 partials per col-half        (4 KB)
    float b2[128];
    float b3[4];
};

__global__ __launch_bounds__(NTHREADS, 1)
void defcorr_mma(const float* __restrict__ Fg,
                 const float* __restrict__ W1, const float* __restrict__ b1,
                 const float* __restrict__ W2, const float* __restrict__ b2,
                 const float* __restrict__ W3, const float* __restrict__ b3,
                 float* __restrict__ out, int n)
{
    __shared__ SmemT sm;

    const int tid  = threadIdx.x;
    const int lane = tid & 31;
    const int warp = tid >> 5;
    const int rg   = warp >> 1;               // row group: 32 rows each
    const int ch   = warp & 1;                // column half: 64 cols each
    const int warpm0 = rg * 32;

    // ---------- stage weights (once) ----------
    // W2^T: [n][k] half; chunk swizzle c' = (c&8) | ((c ^ n) & 7), 16B chunks, 256B rows
    for (int i = tid; i < 128 * 128; i += NTHREADS) {
        const int nn = i >> 7, k = i & 127;
        const int c  = k >> 3;
        const int cs = (c & 8) | ((c ^ nn) & 7);
        const uint32_t off = (uint32_t)nn * 256u + (uint32_t)cs * 16u + (uint32_t)(k & 7) * 2u;
        *reinterpret_cast<__half*>(sm.w2t + off) = __float2half(W2[k * 128 + nn]);
    }
    for (int i = tid; i < 128 * 8; i += NTHREADS) {
        const int nn = i >> 3, k = i & 7;
        sm.w1t[i] = __float2half(k < 7 ? W1[k * 128 + nn] : b1[nn]);
    }
    for (int i = tid; i < 128 * 4; i += NTHREADS) sm.w3[i] = W3[i];
    for (int i = tid; i < 128;     i += NTHREADS) sm.b2[i] = b2[i];
    if (tid < 4) sm.b3[tid] = b3[tid];
    __syncthreads();

    const uint32_t uW2  = smem_u32(sm.w2t);
    const uint32_t uW1  = smem_u32(sm.w1t);
    const uint32_t uInv = smem_u32(sm.inv);

    // ---------- preload layer-1 B fragments (constant for whole kernel) ----------
    uint32_t b1f[16];
    #pragma unroll
    for (int q = 0; q < 4; ++q)
        ldmx4(b1f[4*q], b1f[4*q+1], b1f[4*q+2], b1f[4*q+3],
              uW1 + (uint32_t)(q * 32 + lane) * 16u);

    // per-lane layer-2 ldmatrix address components
    const int rowPart = ((lane >> 4) << 3) | (lane & 7);  // n within 16-row pair
    const int kSel    = (lane >> 3) & 1;                  // 0: k-lo chunk, 1: k-hi chunk
    const uint32_t bAddrBase = uW2 + (uint32_t)rowPart * 256u;

    const int ntiles = (n + 127) >> 7;

    for (int tile = blockIdx.x; tile < ntiles; tile += gridDim.x) {
        __syncthreads();   // protect inv/scal/part reuse across iterations

        // ---------- per-row invariants (threads 0..127) ----------
        if (tid < 128) {
            const int row  = tid;
            const int elem = tile * 128 + row;
            float a = 1.f, b = 0.f, c = 0.f, d = 1.f;
            if (elem < n) {
                const float4 f = reinterpret_cast<const float4*>(Fg)[elem];
                a = f.x; b = f.y; c = f.z; d = f.w;
            }
            const float t0 = a + d, t1 = b - c, t2 = a - d, t3 = b + c;
            const float p = sqrtf(t0*t0 + t1*t1);
            const float q = sqrtf(t2*t2 + t3*t3);
            const float i0 = 0.5f*(p + q) - 1.f;
            const float i1 = 0.5f*fabsf(p - q) - 1.f;
            const float i2 = a*a + c*c - 1.f;
            const float i3 = a*b + c*d;          // == i4
            const float i5 = b*b + d*d - 1.f;
            const float i6 = a*d - b*c - 1.f;
            const float rp  = 1.f / p;
            const float r00 = t0 * rp, r01 = t1 * rp;

            uint4 u;
            u.x = pack_h2(i0, i1);
            u.y = pack_h2(i2, i3);
            u.z = pack_h2(i3, i5);
            u.w = pack_h2(i6, 1.0f);             // k7 = 1.0 (bias input)
            reinterpret_cast<uint4*>(sm.inv)[row] = u;

            float4* s = reinterpret_cast<float4*>(sm.scal + row * 8);
            s[0] = make_float4(a, b, c, d);
            s[1] = make_float4(r00, r01, 0.f, 0.f);
        }
        __syncthreads();

        // ---------- layer 1: two 16-row m-tiles per warp (A register-resident) ----------
        uint32_t aPk[2][32];
        #pragma unroll
        for (int t = 0; t < 2; ++t) {
            uint32_t ai0, ai1;
            ldmx2(ai0, ai1, uInv + (uint32_t)(warpm0 + t*16 + (lane & 15)) * 16u);
            #pragma unroll
            for (int s = 0; s < 8; ++s) {
                float dA[4] = {0.f, 0.f, 0.f, 0.f};
                float dB[4] = {0.f, 0.f, 0.f, 0.f};
                mma_k8(dA, ai0, ai1, b1f[2*s]);
                mma_k8(dB, ai0, ai1, b1f[2*s+1]);
                aPk[t][4*s+0] = pack_h2(fmaxf(dA[0], 0.f), fmaxf(dA[1], 0.f));
                aPk[t][4*s+1] = pack_h2(fmaxf(dA[2], 0.f), fmaxf(dA[3], 0.f));
                aPk[t][4*s+2] = pack_h2(fmaxf(dB[0], 0.f), fmaxf(dB[1], 0.f));
                aPk[t][4*s+3] = pack_h2(fmaxf(dB[2], 0.f), fmaxf(dB[3], 0.f));
            }
        }

        // ---------- layer 2: M32 x N64 per warp (B loaded once for both m-tiles) ----------
        float d2[16][4];                       // [t*8 + local n-tile][4]
        #pragma unroll
        for (int t = 0; t < 16; ++t) { d2[t][0] = d2[t][1] = d2[t][2] = d2[t][3] = 0.f; }

        #pragma unroll
        for (int s = 0; s < 8; ++s) {
            const int c  = 2*s + kSel;
            const int cs = (c & 8) | ((c ^ rowPart) & 7);
            const uint32_t a00 = aPk[0][4*s], a01 = aPk[0][4*s+1],
                           a02 = aPk[0][4*s+2], a03 = aPk[0][4*s+3];
            const uint32_t a10 = aPk[1][4*s], a11 = aPk[1][4*s+1],
                           a12 = aPk[1][4*s+2], a13 = aPk[1][4*s+3];
            #pragma unroll
            for (int j = 0; j < 4; ++j) {       // n-pair index within col half
                uint32_t br0, br1, br2, br3;
                ldmx4(br0, br1, br2, br3,
                      bAddrBase + (uint32_t)((ch*4 + j) * 4096) + (uint32_t)cs * 16u);
                mma_k16(d2[2*j],     a00, a01, a02, a03, br0, br1);
                mma_k16(d2[2*j+1],   a00, a01, a02, a03, br2, br3);
                mma_k16(d2[8+2*j],   a10, a11, a12, a13, br0, br1);
                mma_k16(d2[8+2*j+1], a10, a11, a12, a13, br2, br3);
            }
        }

        // ---------- layer 3 partials over this warp's 64 columns ----------
        float pacc[4][4];                       // [t*2 + rr][o0..o3]
        #pragma unroll
        for (int i = 0; i < 4; ++i) { pacc[i][0]=pacc[i][1]=pacc[i][2]=pacc[i][3]=0.f; }

        #pragma unroll
        for (int t = 0; t < 2; ++t) {
            #pragma unroll
            for (int jl = 0; jl < 8; ++jl) {
                const int n0 = ch*64 + jl*8 + (lane & 3)*2;
                const float bb0 = sm.b2[n0], bb1 = sm.b2[n0 + 1];
                const float* dd = d2[t*8 + jl];
                const float hA0 = fmaxf(dd[0] + bb0, 0.f);
                const float hA1 = fmaxf(dd[1] + bb1, 0.f);
                const float hB0 = fmaxf(dd[2] + bb0, 0.f);
                const float hB1 = fmaxf(dd[3] + bb1, 0.f);
                const float4 w0 = reinterpret_cast<const float4*>(sm.w3)[n0];
                const float4 w1 = reinterpret_cast<const float4*>(sm.w3)[n0 + 1];
                pacc[t*2+0][0] = fmaf(hA0, w0.x, fmaf(hA1, w1.x, pacc[t*2+0][0]));
                pacc[t*2+0][1] = fmaf(hA0, w0.y, fmaf(hA1, w1.y, pacc[t*2+0][1]));
                pacc[t*2+0][2] = fmaf(hA0, w0.z, fmaf(hA1, w1.z, pacc[t*2+0][2]));
                pacc[t*2+0][3] = fmaf(hA0, w0.w, fmaf(hA1, w1.w, pacc[t*2+0][3]));
                pacc[t*2+1][0] = fmaf(hB0, w0.x, fmaf(hB1, w1.x, pacc[t*2+1][0]));
                pacc[t*2+1][1] = fmaf(hB0, w0.y, fmaf(hB1, w1.y, pacc[t*2+1][1]));
                pacc[t*2+1][2] = fmaf(hB0, w0.z, fmaf(hB1, w1.z, pacc[t*2+1][2]));
                pacc[t*2+1][3] = fmaf(hB0, w0.w, fmaf(hB1, w1.w, pacc[t*2+1][3]));
            }
        }
        #pragma unroll
        for (int i = 0; i < 4; ++i) {
            #pragma unroll
            for (int k2 = 0; k2 < 4; ++k2) {
                pacc[i][k2] += __shfl_xor_sync(0xffffffffu, pacc[i][k2], 1);
                pacc[i][k2] += __shfl_xor_sync(0xffffffffu, pacc[i][k2], 2);
            }
        }
        if ((lane & 3) == 0) {
            #pragma unroll
            for (int t = 0; t < 2; ++t) {
                #pragma unroll
                for (int rr = 0; rr < 2; ++rr) {
                    const int row = warpm0 + t*16 + (lane >> 2) + rr*8;
                    reinterpret_cast<float4*>(sm.part)[ch*128 + row] =
                        make_float4(pacc[t*2+rr][0], pacc[t*2+rr][1],
                                    pacc[t*2+rr][2], pacc[t*2+rr][3]);
                }
            }
        }
        __syncthreads();

        // ---------- final epilogue: combine halves, rotate, store ----------
        if (tid < 128) {
            const int row  = tid;
            const int elem = tile * 128 + row;
            if (elem < n) {
                const float4 pa = reinterpret_cast<const float4*>(sm.part)[row];
                const float4 pb = reinterpret_cast<const float4*>(sm.part)[128 + row];
                const float o0 = pa.x + pb.x + sm.b3[0];
                const float o1 = pa.y + pb.y + sm.b3[1];
                const float o2 = pa.z + pb.z + sm.b3[2];
                const float o3 = pa.w + pb.w + sm.b3[3];
                const float4* s = reinterpret_cast<const float4*>(sm.scal + row * 8);
                const float4 fv = s[0];
                const float4 rv = s[1];
                const float x00 = o0, x01 = 0.5f * (o1 + o2), x11 = o3;
                const float r00 = rv.x, r01 = rv.y;
                float4 ov;
                ov.x =  r00*x00 + r01*x01 + fv.x;
                ov.y =  r00*x01 + r01*x11 + fv.y;
                ov.z = -r01*x00 + r00*x01 + fv.z;
                ov.w = -r01*x01 + r00*x11 + fv.w;
                reinterpret_cast<float4*>(out)[elem] = ov;
            }
        }
    }
}

extern "C" void kernel_launch(void* const* d_in, const int* in_sizes, int n_in,
                              void* d_out, int out_size)
{
    const float* F  = (const float*)d_in[0];
    const float* W1 = (const float*)d_in[1];
    const float* b1 = (const float*)d_in[2];
    const float* W2 = (const float*)d_in[3];
    const float* b2 = (const float*)d_in[4];
    const float* W3 = (const float*)d_in[5];
    const float* b3 = (const float*)d_in[6];
    float* out = (float*)d_out;

    const int n = in_sizes[0] / 4;   // number of 2x2 matrices

    defcorr_mma<<<NBLOCKS, NTHREADS>>>(F, W1, b1, W2, b2, W3, b3, out, n);
}

// round 5
// speedup vs baseline: 1.0937x; 1.0937x over previous
#include <cuda_runtime.h>
#include <cuda_fp16.h>
#include <cstdint>

#define NTHREADS 256
#define NBLOCKS  296

// ---------------- PTX helpers ----------------
__device__ __forceinline__ uint32_t smem_u32(const void* p) {
    uint32_t a;
    asm("{ .reg .u64 t; cvta.to.shared.u64 t, %1; cvt.u32.u64 %0, t; }" : "=r"(a) : "l"(p));
    return a;
}
__device__ __forceinline__ void ldmx2(uint32_t& r0, uint32_t& r1, uint32_t addr) {
    asm volatile("ldmatrix.sync.aligned.m8n8.x2.shared.b16 {%0,%1}, [%2];"
                 : "=r"(r0), "=r"(r1) : "r"(addr));
}
__device__ __forceinline__ void ldmx4(uint32_t& r0, uint32_t& r1, uint32_t& r2, uint32_t& r3,
                                      uint32_t addr) {
    asm volatile("ldmatrix.sync.aligned.m8n8.x4.shared.b16 {%0,%1,%2,%3}, [%4];"
                 : "=r"(r0), "=r"(r1), "=r"(r2), "=r"(r3) : "r"(addr));
}
__device__ __forceinline__ void mma_k8(float* d, uint32_t a0, uint32_t a1, uint32_t b0) {
    asm volatile("mma.sync.aligned.m16n8k8.row.col.f32.f16.f16.f32 "
                 "{%0,%1,%2,%3}, {%4,%5}, {%6}, {%0,%1,%2,%3};"
                 : "+f"(d[0]), "+f"(d[1]), "+f"(d[2]), "+f"(d[3])
                 : "r"(a0), "r"(a1), "r"(b0));
}
__device__ __forceinline__ void mma_k16(float* d, uint32_t a0, uint32_t a1, uint32_t a2,
                                        uint32_t a3, uint32_t b0, uint32_t b1) {
    asm volatile("mma.sync.aligned.m16n8k16.row.col.f32.f16.f16.f32 "
                 "{%0,%1,%2,%3}, {%4,%5,%6,%7}, {%8,%9}, {%0,%1,%2,%3};"
                 : "+f"(d[0]), "+f"(d[1]), "+f"(d[2]), "+f"(d[3])
                 : "r"(a0), "r"(a1), "r"(a2), "r"(a3), "r"(b0), "r"(b1));
}
__device__ __forceinline__ uint32_t pack_h2(float x, float y) {
    __half2 h = __floats2half2_rn(x, y);          // low half = x
    return *reinterpret_cast<uint32_t*>(&h);
}

// ---------------- shared memory ----------------
struct SmemT {
    __align__(16) uint8_t w2t[128 * 256];   // W2^T [n][k] half, swizzled 256B rows (32 KB)
    __align__(16) __half  w1t[128 * 8];     // W1^T [n][k0..6], k7 = b1[n]          (2 KB)
    __align__(16) __half  inv[128 * 8];     // per-row invariants (k7 = 1.0)        (2 KB)
    __align__(16) float   scal[128 * 8];    // per-row {a,b,c,d,r00,r01,-,-}        (4 KB)
    __align__(16) float   w3[128 * 4];      // W3 rows as float4                    (2 KB)
    __align__(16) float   part[2 * 128 * 4];// layer-3 partials per col-half        (4 KB)
    float b2[128];
    float b3[4];
};

__global__ __launch_bounds__(NTHREADS, 2)
void defcorr_mma(const float* __restrict__ Fg,
                 const float* __restrict__ W1, const float* __restrict__ b1,
                 const float* __restrict__ W2, const float* __restrict__ b2,
                 const float* __restrict__ W3, const float* __restrict__ b3,
                 float* __restrict__ out, int n)
{
    __shared__ SmemT sm;

    const int tid  = threadIdx.x;
    const int lane = tid & 31;
    const int warp = tid >> 5;
    const int rg   = warp >> 1;               // row group: 32 rows each
    const int ch   = warp & 1;                // column half: 64 cols each
    const int warpm0 = rg * 32;

    // ---------- stage weights (once) ----------
    // W2^T: [n][k] half; chunk swizzle c' = (c&8) | ((c ^ n) & 7), 16B chunks, 256B rows
    for (int i = tid; i < 128 * 128; i += NTHREADS) {
        const int nn = i >> 7, k = i & 127;
        const int c  = k >> 3;
        const int cs = (c & 8) | ((c ^ nn) & 7);
        const uint32_t off = (uint32_t)nn * 256u + (uint32_t)cs * 16u + (uint32_t)(k & 7) * 2u;
        *reinterpret_cast<__half*>(sm.w2t + off) = __float2half(W2[k * 128 + nn]);
    }
    for (int i = tid; i < 128 * 8; i += NTHREADS) {
        const int nn = i >> 3, k = i & 7;
        sm.w1t[i] = __float2half(k < 7 ? W1[k * 128 + nn] : b1[nn]);
    }
    for (int i = tid; i < 128 * 4; i += NTHREADS) sm.w3[i] = W3[i];
    for (int i = tid; i < 128;     i += NTHREADS) sm.b2[i] = b2[i];
    if (tid < 4) sm.b3[tid] = b3[tid];
    __syncthreads();

    const uint32_t uW2  = smem_u32(sm.w2t);
    const uint32_t uW1  = smem_u32(sm.w1t);
    const uint32_t uInv = smem_u32(sm.inv);

    // per-lane layer-2 ldmatrix address components
    const int rowPart = ((lane >> 4) << 3) | (lane & 7);  // n within 16-row pair
    const int kSel    = (lane >> 3) & 1;                  // 0: k-lo chunk, 1: k-hi chunk
    const uint32_t bAddrBase  = uW2 + (uint32_t)rowPart * 256u + (uint32_t)(ch * 4) * 4096u;
    const uint32_t w1AddrBase = uW1 + (uint32_t)(lane & 15) * 16u;

    const int ntiles = (n + 127) >> 7;

    for (int tile = blockIdx.x; tile < ntiles; tile += gridDim.x) {
        __syncthreads();   // protect inv/scal/part reuse across iterations

        // ---------- per-row invariants (threads 0..127) ----------
        if (tid < 128) {
            const int row  = tid;
            const int elem = tile * 128 + row;
            float a = 1.f, b = 0.f, c = 0.f, d = 1.f;
            if (elem < n) {
                const float4 f = reinterpret_cast<const float4*>(Fg)[elem];
                a = f.x; b = f.y; c = f.z; d = f.w;
            }
            const float t0 = a + d, t1 = b - c, t2 = a - d, t3 = b + c;
            const float p = sqrtf(t0*t0 + t1*t1);
            const float q = sqrtf(t2*t2 + t3*t3);
            const float i0 = 0.5f*(p + q) - 1.f;
            const float i1 = 0.5f*fabsf(p - q) - 1.f;
            const float i2 = a*a + c*c - 1.f;
            const float i3 = a*b + c*d;          // == i4
            const float i5 = b*b + d*d - 1.f;
            const float i6 = a*d - b*c - 1.f;
            const float rp  = 1.f / p;
            const float r00 = t0 * rp, r01 = t1 * rp;

            uint4 u;
            u.x = pack_h2(i0, i1);
            u.y = pack_h2(i2, i3);
            u.z = pack_h2(i3, i5);
            u.w = pack_h2(i6, 1.0f);             // k7 = 1.0 (bias input)
            reinterpret_cast<uint4*>(sm.inv)[row] = u;

            float4* s = reinterpret_cast<float4*>(sm.scal + row * 8);
            s[0] = make_float4(a, b, c, d);
            s[1] = make_float4(r00, r01, 0.f, 0.f);
        }
        __syncthreads();

        // ---------- A-inputs for layer 1 (both 16-row m-tiles, register resident) ----------
        uint32_t ai[2][2];
        ldmx2(ai[0][0], ai[0][1], uInv + (uint32_t)(warpm0      + (lane & 15)) * 16u);
        ldmx2(ai[1][0], ai[1][1], uInv + (uint32_t)(warpm0 + 16 + (lane & 15)) * 16u);

        // ---------- fused layer1 + layer2, per k-step ----------
        float d2[16][4];                       // [t*8 + local n-tile][4]
        #pragma unroll
        for (int t = 0; t < 16; ++t) { d2[t][0] = d2[t][1] = d2[t][2] = d2[t][3] = 0.f; }

        #pragma unroll
        for (int s = 0; s < 8; ++s) {
            // layer-1 B frags for k-step s (n-tiles 2s, 2s+1)
            uint32_t bb0, bb1;
            ldmx2(bb0, bb1, w1AddrBase + (uint32_t)(s * 16) * 16u);

            // h1 columns 16s..16s+15 for both m-tiles, packed fp16
            uint32_t pk[2][4];
            #pragma unroll
            for (int t = 0; t < 2; ++t) {
                float dA[4] = {0.f, 0.f, 0.f, 0.f};
                float dB[4] = {0.f, 0.f, 0.f, 0.f};
                mma_k8(dA, ai[t][0], ai[t][1], bb0);
                mma_k8(dB, ai[t][0], ai[t][1], bb1);
                pk[t][0] = pack_h2(fmaxf(dA[0], 0.f), fmaxf(dA[1], 0.f));
                pk[t][1] = pack_h2(fmaxf(dA[2], 0.f), fmaxf(dA[3], 0.f));
                pk[t][2] = pack_h2(fmaxf(dB[0], 0.f), fmaxf(dB[1], 0.f));
                pk[t][3] = pack_h2(fmaxf(dB[2], 0.f), fmaxf(dB[3], 0.f));
            }

            // layer-2: consume immediately against this warp's 64 columns
            const int c  = 2*s + kSel;
            const int cs = (c & 8) | ((c ^ rowPart) & 7);
            #pragma unroll
            for (int j = 0; j < 4; ++j) {       // n-pair index within col half
                uint32_t br0, br1, br2, br3;
                ldmx4(br0, br1, br2, br3,
                      bAddrBase + (uint32_t)(j * 4096) + (uint32_t)cs * 16u);
                mma_k16(d2[2*j],     pk[0][0], pk[0][1], pk[0][2], pk[0][3], br0, br1);
                mma_k16(d2[2*j+1],   pk[0][0], pk[0][1], pk[0][2], pk[0][3], br2, br3);
                mma_k16(d2[8+2*j],   pk[1][0], pk[1][1], pk[1][2], pk[1][3], br0, br1);
                mma_k16(d2[8+2*j+1], pk[1][0], pk[1][1], pk[1][2], pk[1][3], br2, br3);
            }
        }

        // ---------- layer 3 partials over this warp's 64 columns ----------
        float pacc[4][4];                       // [t*2 + rr][o0..o3]
        #pragma unroll
        for (int i = 0; i < 4; ++i) { pacc[i][0]=pacc[i][1]=pacc[i][2]=pacc[i][3]=0.f; }

        #pragma unroll
        for (int t = 0; t < 2; ++t) {
            #pragma unroll
            for (int jl = 0; jl < 8; ++jl) {
                const int n0 = ch*64 + jl*8 + (lane & 3)*2;
                const float bb0 = sm.b2[n0], bb1 = sm.b2[n0 + 1];
                const float* dd = d2[t*8 + jl];
                const float hA0 = fmaxf(dd[0] + bb0, 0.f);
                const float hA1 = fmaxf(dd[1] + bb1, 0.f);
                const float hB0 = fmaxf(dd[2] + bb0, 0.f);
                const float hB1 = fmaxf(dd[3] + bb1, 0.f);
                const float4 w0 = reinterpret_cast<const float4*>(sm.w3)[n0];
                const float4 w1 = reinterpret_cast<const float4*>(sm.w3)[n0 + 1];
                pacc[t*2+0][0] = fmaf(hA0, w0.x, fmaf(hA1, w1.x, pacc[t*2+0][0]));
                pacc[t*2+0][1] = fmaf(hA0, w0.y, fmaf(hA1, w1.y, pacc[t*2+0][1]));
                pacc[t*2+0][2] = fmaf(hA0, w0.z, fmaf(hA1, w1.z, pacc[t*2+0][2]));
                pacc[t*2+0][3] = fmaf(hA0, w0.w, fmaf(hA1, w1.w, pacc[t*2+0][3]));
                pacc[t*2+1][0] = fmaf(hB0, w0.x, fmaf(hB1, w1.x, pacc[t*2+1][0]));
                pacc[t*2+1][1] = fmaf(hB0, w0.y, fmaf(hB1, w1.y, pacc[t*2+1][1]));
                pacc[t*2+1][2] = fmaf(hB0, w0.z, fmaf(hB1, w1.z, pacc[t*2+1][2]));
                pacc[t*2+1][3] = fmaf(hB0, w0.w, fmaf(hB1, w1.w, pacc[t*2+1][3]));
            }
        }
        #pragma unroll
        for (int i = 0; i < 4; ++i) {
            #pragma unroll
            for (int k2 = 0; k2 < 4; ++k2) {
                pacc[i][k2] += __shfl_xor_sync(0xffffffffu, pacc[i][k2], 1);
                pacc[i][k2] += __shfl_xor_sync(0xffffffffu, pacc[i][k2], 2);
            }
        }
        if ((lane & 3) == 0) {
            #pragma unroll
            for (int t = 0; t < 2; ++t) {
                #pragma unroll
                for (int rr = 0; rr < 2; ++rr) {
                    const int row = warpm0 + t*16 + (lane >> 2) + rr*8;
                    reinterpret_cast<float4*>(sm.part)[ch*128 + row] =
                        make_float4(pacc[t*2+rr][0], pacc[t*2+rr][1],
                                    pacc[t*2+rr][2], pacc[t*2+rr][3]);
                }
            }
        }
        __syncthreads();

        // ---------- final epilogue: combine halves, rotate, store ----------
        if (tid < 128) {
            const int row  = tid;
            const int elem = tile * 128 + row;
            if (elem < n) {
                const float4 pa = reinterpret_cast<const float4*>(sm.part)[row];
                const float4 pb = reinterpret_cast<const float4*>(sm.part)[128 + row];
                const float o0 = pa.x + pb.x + sm.b3[0];
                const float o1 = pa.y + pb.y + sm.b3[1];
                const float o2 = pa.z + pb.z + sm.b3[2];
                const float o3 = pa.w + pb.w + sm.b3[3];
                const float4* s = reinterpret_cast<const float4*>(sm.scal + row * 8);
                const float4 fv = s[0];
                const float4 rv = s[1];
                const float x00 = o0, x01 = 0.5f * (o1 + o2), x11 = o3;
                const float r00 = rv.x, r01 = rv.y;
                float4 ov;
                ov.x =  r00*x00 + r01*x01 + fv.x;
                ov.y =  r00*x01 + r01*x11 + fv.y;
                ov.z = -r01*x00 + r00*x01 + fv.z;
                ov.w = -r01*x01 + r00*x11 + fv.w;
                reinterpret_cast<float4*>(out)[elem] = ov;
            }
        }
    }
}

extern "C" void kernel_launch(void* const* d_in, const int* in_sizes, int n_in,
                              void* d_out, int out_size)
{
    const float* F  = (const float*)d_in[0];
    const float* W1 = (const float*)d_in[1];
    const float* b1 = (const float*)d_in[2];
    const float* W2 = (const float*)d_in[3];
    const float* b2 = (const float*)d_in[4];
    const float* W3 = (const float*)d_in[5];
    const float* b3 = (const float*)d_in[6];
    float* out = (float*)d_out;

    const int n = in_sizes[0] / 4;   // number of 2x2 matrices

    defcorr_mma<<<NBLOCKS, NTHREADS>>>(F, W1, b1, W2, b2, W3, b3, out, n);
}